// round 12
// baseline (speedup 1.0000x reference)
#include <cuda_runtime.h>

#define NATOM 30000
#define NNJ 12
#define KD 32
#define FD 128
#define LDA 132

// sB layout: [32 k][152 cols]; cols: s [0,16), p a*16+[16,64), d a*16+[64,144), pads zeroed
#define LDB 152
#define SB_FLOATS (32 * LDB)           // 4864
#define FEA_LD 17
#define SFEA_FLOATS (3 * 128 * FEA_LD) // 6528

#define NP_BLK 1407   // ceil(30000*3/64)
#define ND_BLK 2344   // ceil(30000*5/64)

// ---------------- device scratch ----------------
__device__ float g_sfea[NATOM * FD];
__device__ float g_pfea[NATOM * FD];
__device__ float g_dfea[NATOM * FD];
__device__ float g_allp[NATOM * 3 * FD];   // [n][a][f]
__device__ float g_alld[NATOM * 5 * FD];   // [n][a][f]
__device__ float g_Mp[FD * FD];            // P1 @ P2^T
__device__ float g_Md[FD * FD];            // D1 @ D2^T
__device__ float g_rowp[NATOM * 3];
__device__ float g_rowd[NATOM * 5];

__device__ __forceinline__ float siluf(float x) {
    return x / (1.0f + __expf(-x));
}

__device__ __forceinline__ unsigned tf32r(float x) {
    unsigned u;
    asm("cvt.rna.tf32.f32 %0, %1;" : "=r"(u) : "f"(x));
    return u;
}

__device__ __forceinline__ void mma_tf32(float c[4], const unsigned a[4],
                                         unsigned b0, unsigned b1) {
    asm volatile(
        "mma.sync.aligned.m16n8k8.row.col.f32.tf32.tf32.f32 "
        "{%0,%1,%2,%3},{%4,%5,%6,%7},{%8,%9},{%0,%1,%2,%3};"
        : "+f"(c[0]), "+f"(c[1]), "+f"(c[2]), "+f"(c[3])
        : "r"(a[0]), "r"(a[1]), "r"(a[2]), "r"(a[3]), "r"(b0), "r"(b1));
}

// ---------------- K1: Mp = P1 @ P2^T, Md = D1 @ D2^T ----------------
__global__ __launch_bounds__(128)
void k_mmt(const float* __restrict__ P1, const float* __restrict__ P2,
           const float* __restrict__ D1, const float* __restrict__ D2)
{
    const float* A = blockIdx.y ? D1 : P1;
    const float* B = blockIdx.y ? D2 : P2;
    float* M = blockIdx.y ? g_Md : g_Mp;

    __shared__ float smA[8 * FD];
    __shared__ float smB[16 * LDA];
    int t = threadIdx.x;
    int i0 = blockIdx.x * 8;

#pragma unroll
    for (int r = 0; r < 2; r++) {
        int e = t + r * 128;
        ((float4*)smA)[e] = ((const float4*)A)[i0 * 32 + e];
    }

    float acc[8];
#pragma unroll
    for (int i = 0; i < 8; i++) acc[i] = 0.f;

    for (int g0 = 0; g0 < FD; g0 += 16) {
        __syncthreads();
#pragma unroll
        for (int r = 0; r < 4; r++) {
            int e = t + r * 128;
            int j = e >> 2, q = e & 3;
            float4 v = ((const float4*)B)[j * 32 + (g0 >> 2) + q];
            smB[(q * 4 + 0) * LDA + j] = v.x;
            smB[(q * 4 + 1) * LDA + j] = v.y;
            smB[(q * 4 + 2) * LDA + j] = v.z;
            smB[(q * 4 + 3) * LDA + j] = v.w;
        }
        __syncthreads();
#pragma unroll
        for (int gl = 0; gl < 16; gl++) {
            float b = smB[gl * LDA + t];
#pragma unroll
            for (int i = 0; i < 8; i++)
                acc[i] = fmaf(smA[i * FD + g0 + gl], b, acc[i]);
        }
    }
#pragma unroll
    for (int i = 0; i < 8; i++) M[(i0 + i) * FD + t] = acc[i];
}

// ---------------- K2: fused ResMLP via tf32 mma, smem-staged W (16-wide) ----------------
struct MlpArgs {
    const float* wr[4]; const float* br[4];
    const float* w1[4]; const float* b1[4];
};

__device__ __forceinline__ void mma_gemm_pass(const float* __restrict__ W,
                                              float acc[8][4],
                                              const unsigned* smA, unsigned* smW,
                                              int t, int mt, int nh, int gid, int tig)
{
#pragma unroll
    for (int nt = 0; nt < 8; nt++)
#pragma unroll
        for (int c = 0; c < 4; c++) acc[nt][c] = 0.f;

    int wrow = t >> 1, wq = (t & 1) * 8;
    int r0 = mt * 16 + gid;

    for (int k0 = 0; k0 < FD; k0 += 16) {
        __syncthreads();          // smW reuse from previous slice
        float4 v0 = *(const float4*)&W[wrow * FD + k0 + wq];
        float4 v1 = *(const float4*)&W[wrow * FD + k0 + wq + 4];
        smW[(wq + 0) * 132 + wrow] = tf32r(v0.x);
        smW[(wq + 1) * 132 + wrow] = tf32r(v0.y);
        smW[(wq + 2) * 132 + wrow] = tf32r(v0.z);
        smW[(wq + 3) * 132 + wrow] = tf32r(v0.w);
        smW[(wq + 4) * 132 + wrow] = tf32r(v1.x);
        smW[(wq + 5) * 132 + wrow] = tf32r(v1.y);
        smW[(wq + 6) * 132 + wrow] = tf32r(v1.z);
        smW[(wq + 7) * 132 + wrow] = tf32r(v1.w);
        __syncthreads();

#pragma unroll
        for (int kk = 0; kk < 16; kk += 8) {
            unsigned a[4];
            a[0] = smA[r0 * LDA + k0 + kk + tig];
            a[1] = smA[(r0 + 8) * LDA + k0 + kk + tig];
            a[2] = smA[r0 * LDA + k0 + kk + tig + 4];
            a[3] = smA[(r0 + 8) * LDA + k0 + kk + tig + 4];
#pragma unroll
            for (int nt = 0; nt < 8; nt++) {
                int n0 = nh * 64 + nt * 8;
                unsigned b0 = smW[(kk + tig) * 132 + n0 + gid];
                unsigned b1 = smW[(kk + tig + 4) * 132 + n0 + gid];
                mma_tf32(acc[nt], a, b0, b1);
            }
        }
    }
    __syncthreads();
}

__global__ __launch_bounds__(256)
void k_resmlp_mma(const float* __restrict__ x, MlpArgs args, float* __restrict__ out)
{
    __shared__ unsigned smA[64 * LDA];
    __shared__ unsigned smW[16 * 132];

    int ch = blockIdx.y;
    const float* wr = args.wr[ch];
    const float* brp = args.br[ch];
    const float* w1 = args.w1[ch];
    const float* b1p = args.b1[ch];
    float* dst = (ch == 0) ? out : (ch == 1) ? g_sfea : (ch == 2) ? g_pfea : g_dfea;

    int row0 = blockIdx.x * 64;
    int t = threadIdx.x;
    int w = t >> 5, lane = t & 31;
    int mt = w & 3, nh = w >> 2;
    int gid = lane >> 2, tig = lane & 3;

#pragma unroll
    for (int r = 0; r < 8; r++) {
        int e = t + r * 256;
        int m = e >> 5, c4 = e & 31;
        int gr = row0 + m;
        float4 v = make_float4(0.f, 0.f, 0.f, 0.f);
        if (gr < NATOM) v = ((const float4*)x)[gr * 32 + c4];
        smA[m * LDA + c4 * 4 + 0] = tf32r(siluf(v.x));
        smA[m * LDA + c4 * 4 + 1] = tf32r(siluf(v.y));
        smA[m * LDA + c4 * 4 + 2] = tf32r(siluf(v.z));
        smA[m * LDA + c4 * 4 + 3] = tf32r(siluf(v.w));
    }

    float acc[8][4];
    mma_gemm_pass(wr, acc, smA, smW, t, mt, nh, gid, tig);

    {
        int r0 = row0 + mt * 16 + gid;
        int r1 = r0 + 8;
#pragma unroll
        for (int nt = 0; nt < 8; nt++) {
            int c = nh * 64 + nt * 8 + 2 * tig;
            float2 br2 = *(const float2*)&brp[c];
            float2 x0 = make_float2(0.f, 0.f), x1 = x0;
            if (r0 < NATOM) x0 = *(const float2*)&x[r0 * FD + c];
            if (r1 < NATOM) x1 = *(const float2*)&x[r1 * FD + c];
            int lr0 = mt * 16 + gid, lr1 = lr0 + 8;
            smA[lr0 * LDA + c]     = tf32r(siluf(acc[nt][0] + x0.x + br2.x));
            smA[lr0 * LDA + c + 1] = tf32r(siluf(acc[nt][1] + x0.y + br2.y));
            smA[lr1 * LDA + c]     = tf32r(siluf(acc[nt][2] + x1.x + br2.x));
            smA[lr1 * LDA + c + 1] = tf32r(siluf(acc[nt][3] + x1.y + br2.y));
        }
    }

    mma_gemm_pass(w1, acc, smA, smW, t, mt, nh, gid, tig);

    {
        int r0 = row0 + mt * 16 + gid;
        int r1 = r0 + 8;
#pragma unroll
        for (int nt = 0; nt < 8; nt++) {
            int c = nh * 64 + nt * 8 + 2 * tig;
            float2 b2 = *(const float2*)&b1p[c];
            if (r0 < NATOM)
                *(float2*)&dst[r0 * FD + c] =
                    make_float2(acc[nt][0] + b2.x, acc[nt][1] + b2.y);
            if (r1 < NATOM)
                *(float2*)&dst[r1 * FD + c] =
                    make_float2(acc[nt][2] + b2.x, acc[nt][3] + b2.y);
        }
    }
}

// ---------------- K3: env via tf32 mma, software-pipelined ----------------
__global__ __launch_bounds__(128)
void k_env_mma(const int* __restrict__ nbr,
               const float* __restrict__ gs, const float* __restrict__ gp,
               const float* __restrict__ gd,
               const float* __restrict__ Gs, const float* __restrict__ Gp,
               const float* __restrict__ Gd,
               float* __restrict__ out)
{
    __shared__ unsigned sBu[SB_FLOATS];
    __shared__ float sFea[SFEA_FLOATS];

    int t = threadIdx.x;
    int w = t >> 5;
    int lane = t & 31;
    int gid = lane >> 2;
    int tig = lane & 3;

    // zero once: covers all pad columns / pad j entries (never overwritten later)
    for (int e = t; e < SB_FLOATS; e += 128) sBu[e] = 0u;
    for (int e = t; e < SFEA_FLOATS; e += 128) sFea[e] = 0.f;

    const float4* gs4 = (const float4*)gs;
    const float4* gp4 = (const float4*)gp;
    const float4* gd4 = (const float4*)gd;

    // ---- prologue prefetch (registers) ----
    int n = blockIdx.x;
    int4 jA, jB, jC;
    float4 pgs, pgp[3], pgd[4];
    {
        const int4* nb4 = (const int4*)(nbr + n * NNJ);
        jA = nb4[0]; jB = nb4[1]; jC = nb4[2];
        if (t < 96) pgs = gs4[(size_t)n * 96 + t];
#pragma unroll
        for (int r = 0; r < 3; r++) {
            int e = t + r * 128;
            if (e < 288) pgp[r] = gp4[(size_t)n * 288 + e];
        }
#pragma unroll
        for (int r = 0; r < 4; r++) {
            int e = t + r * 128;
            if (e < 480) pgd[r] = gd4[(size_t)n * 480 + e];
        }
    }

    for (; n < NATOM; n += gridDim.x) {
        int jn[NNJ] = {jA.x, jA.y, jA.z, jA.w, jB.x, jB.y, jB.z, jB.w,
                       jC.x, jC.y, jC.z, jC.w};

        // fea gathers first (longest-latency loads of the stage phase)
        {
            float* r0 = sFea + t * FEA_LD;
            float* r1 = sFea + 128 * FEA_LD + t * FEA_LD;
            float* r2 = sFea + 256 * FEA_LD + t * FEA_LD;
#pragma unroll
            for (int j = 0; j < NNJ; j++) {
                size_t off = (size_t)jn[j] * FD + t;
                r0[j] = g_sfea[off];
                r1[j] = g_pfea[off];
                r2[j] = g_dfea[off];
            }
        }
        // gs from regs
        if (t < 96) {
            int j = t >> 3, q = t & 7;
            int base = (q * 4) * LDB + j;
            sBu[base]           = tf32r(pgs.x);
            sBu[base + LDB]     = tf32r(pgs.y);
            sBu[base + 2 * LDB] = tf32r(pgs.z);
            sBu[base + 3 * LDB] = tf32r(pgs.w);
        }
        // gp from regs
#pragma unroll
        for (int r = 0; r < 3; r++) {
            int e = t + r * 128;
            if (e < 288) {
                float vv[4] = {pgp[r].x, pgp[r].y, pgp[r].z, pgp[r].w};
#pragma unroll
                for (int u = 0; u < 4; u++) {
                    int idx = e * 4 + u;
                    int j = idx / 96, rr = idx % 96;
                    int k = rr / 3, a = rr % 3;
                    sBu[k * LDB + 16 + a * 16 + j] = tf32r(vv[u]);
                }
            }
        }
        // gd from regs
#pragma unroll
        for (int r = 0; r < 4; r++) {
            int e = t + r * 128;
            if (e < 480) {
                float vv[4] = {pgd[r].x, pgd[r].y, pgd[r].z, pgd[r].w};
#pragma unroll
                for (int u = 0; u < 4; u++) {
                    int idx = e * 4 + u;
                    int j = idx / 160, rr = idx % 160;
                    int k = rr / 5, a = rr % 5;
                    sBu[k * LDB + 64 + a * 16 + j] = tf32r(vv[u]);
                }
            }
        }
        __syncthreads();

        // ---- prefetch next atom during compute ----
        int nn = n + gridDim.x;
        if (nn < NATOM) {
            const int4* nb4 = (const int4*)(nbr + nn * NNJ);
            jA = nb4[0]; jB = nb4[1]; jC = nb4[2];
            if (t < 96) pgs = gs4[(size_t)nn * 96 + t];
#pragma unroll
            for (int r = 0; r < 3; r++) {
                int e = t + r * 128;
                if (e < 288) pgp[r] = gp4[(size_t)nn * 288 + e];
            }
#pragma unroll
            for (int r = 0; r < 4; r++) {
                int e = t + r * 128;
                if (e < 480) pgd[r] = gd4[(size_t)nn * 480 + e];
            }
        }

        // ---- compute: per-channel A reload (G is L1-hot) ----
        const float* Gtab[3] = {Gs, Gp, Gd};
#pragma unroll
        for (int ch = 0; ch < 3; ch++) {
            const float* G = Gtab[ch];
            unsigned Ac[2][4][4];
#pragma unroll
            for (int mt = 0; mt < 2; mt++) {
#pragma unroll
                for (int k4 = 0; k4 < 4; k4++) {
                    int r0 = w * 32 + mt * 16 + gid;
                    int c0 = k4 * 8 + tig;
                    Ac[mt][k4][0] = tf32r(G[r0 * 32 + c0]);
                    Ac[mt][k4][1] = tf32r(G[(r0 + 8) * 32 + c0]);
                    Ac[mt][k4][2] = tf32r(G[r0 * 32 + c0 + 4]);
                    Ac[mt][k4][3] = tf32r(G[(r0 + 8) * 32 + c0 + 4]);
                }
            }
            const int NA = (ch == 0) ? 1 : (ch == 1) ? 3 : 5;
            const int CB = (ch == 0) ? 0 : (ch == 1) ? 16 : 64;
            const float* fbase = sFea + ch * (128 * FEA_LD);
#pragma unroll
            for (int a = 0; a < NA; a++) {
                float Pl[2][2] = {{0.f, 0.f}, {0.f, 0.f}};
#pragma unroll
                for (int half = 0; half < 2; half++) {
                    int cb = CB + a * 16 + half * 8;
                    unsigned bf[8];
#pragma unroll
                    for (int k4 = 0; k4 < 4; k4++) {
                        bf[2 * k4]     = sBu[(k4 * 8 + tig) * LDB + cb + gid];
                        bf[2 * k4 + 1] = sBu[(k4 * 8 + tig + 4) * LDB + cb + gid];
                    }
                    int j0 = half * 8 + 2 * tig;
#pragma unroll
                    for (int mt = 0; mt < 2; mt++) {
                        float C[4] = {0.f, 0.f, 0.f, 0.f};
#pragma unroll
                        for (int k4 = 0; k4 < 4; k4++)
                            mma_tf32(C, Ac[mt][k4], bf[2 * k4], bf[2 * k4 + 1]);
                        int r = w * 32 + mt * 16 + gid;
                        const float* fr0 = fbase + r * FEA_LD;
                        const float* fr1 = fr0 + 8 * FEA_LD;
                        Pl[mt][0] += C[0] * fr0[j0] + C[1] * fr0[j0 + 1];
                        Pl[mt][1] += C[2] * fr1[j0] + C[3] * fr1[j0 + 1];
                    }
                }
                // reduce + store this (ch, a)
#pragma unroll
                for (int mt = 0; mt < 2; mt++) {
#pragma unroll
                    for (int rr = 0; rr < 2; rr++) {
                        float v = Pl[mt][rr];
                        v += __shfl_xor_sync(0xffffffffu, v, 1);
                        v += __shfl_xor_sync(0xffffffffu, v, 2);
                        if (tig == 0) {
                            int r = w * 32 + mt * 16 + rr * 8 + gid;
                            if (ch == 0)
                                out[(size_t)n * FD + r] += v;
                            else if (ch == 1)
                                g_allp[((size_t)n * 3 + a) * FD + r] = v;
                            else
                                g_alld[((size_t)n * 5 + a) * FD + r] = v;
                        }
                    }
                }
            }
        }

        __syncthreads();
    }
}

// ---------------- K4: rowdot[r] = v_r . (M v_r), merged p+d, smem-staged M ----------------
__global__ __launch_bounds__(256)
void k_quad_mma()
{
    int bid = blockIdx.x;
    int which = (bid >= NP_BLK) ? 1 : 0;
    const float* V = which ? g_alld : g_allp;
    const float* M = which ? g_Md : g_Mp;
    float* rowdot = which ? g_rowd : g_rowp;
    int R = which ? NATOM * 5 : NATOM * 3;
    int row0 = (which ? bid - NP_BLK : bid) * 64;

    __shared__ unsigned smA[64 * LDA];
    __shared__ unsigned smW[16 * 132];
    __shared__ float sPart[2][4][16];

    int t = threadIdx.x;
    int w = t >> 5, lane = t & 31;
    int mt = w & 3, nh = w >> 2;
    int gid = lane >> 2, tig = lane & 3;

#pragma unroll
    for (int r = 0; r < 8; r++) {
        int e = t + r * 256;
        int m = e >> 5, c4 = e & 31;
        int gr = row0 + m;
        float4 v = make_float4(0.f, 0.f, 0.f, 0.f);
        if (gr < R) v = ((const float4*)V)[gr * 32 + c4];
        smA[m * LDA + c4 * 4 + 0] = tf32r(v.x);
        smA[m * LDA + c4 * 4 + 1] = tf32r(v.y);
        smA[m * LDA + c4 * 4 + 2] = tf32r(v.z);
        smA[m * LDA + c4 * 4 + 3] = tf32r(v.w);
    }

    float acc[8][4];
#pragma unroll
    for (int nt = 0; nt < 8; nt++)
#pragma unroll
        for (int c = 0; c < 4; c++) acc[nt][c] = 0.f;

    int kr = t >> 4, c8 = (t & 15) * 8;
    int r0 = mt * 16 + gid;

    for (int k0 = 0; k0 < FD; k0 += 16) {
        __syncthreads();
        float4 v0 = *(const float4*)&M[(k0 + kr) * FD + c8];
        float4 v1 = *(const float4*)&M[(k0 + kr) * FD + c8 + 4];
        smW[kr * 132 + c8 + 0] = tf32r(v0.x);
        smW[kr * 132 + c8 + 1] = tf32r(v0.y);
        smW[kr * 132 + c8 + 2] = tf32r(v0.z);
        smW[kr * 132 + c8 + 3] = tf32r(v0.w);
        smW[kr * 132 + c8 + 4] = tf32r(v1.x);
        smW[kr * 132 + c8 + 5] = tf32r(v1.y);
        smW[kr * 132 + c8 + 6] = tf32r(v1.z);
        smW[kr * 132 + c8 + 7] = tf32r(v1.w);
        __syncthreads();

#pragma unroll
        for (int kk = 0; kk < 16; kk += 8) {
            unsigned a[4];
            a[0] = smA[r0 * LDA + k0 + kk + tig];
            a[1] = smA[(r0 + 8) * LDA + k0 + kk + tig];
            a[2] = smA[r0 * LDA + k0 + kk + tig + 4];
            a[3] = smA[(r0 + 8) * LDA + k0 + kk + tig + 4];
#pragma unroll
            for (int nt = 0; nt < 8; nt++) {
                int n0 = nh * 64 + nt * 8;
                unsigned b0 = smW[(kk + tig) * 132 + n0 + gid];
                unsigned b1 = smW[(kk + tig + 4) * 132 + n0 + gid];
                mma_tf32(acc[nt], a, b0, b1);
            }
        }
    }

    // fused row dot vs smem V (tf32-truncated)
    float d0 = 0.f, d1 = 0.f;
    {
        int lr0 = mt * 16 + gid, lr1 = lr0 + 8;
#pragma unroll
        for (int nt = 0; nt < 8; nt++) {
            int c = nh * 64 + nt * 8 + 2 * tig;
            float v00 = __uint_as_float(smA[lr0 * LDA + c]);
            float v01 = __uint_as_float(smA[lr0 * LDA + c + 1]);
            float v10 = __uint_as_float(smA[lr1 * LDA + c]);
            float v11 = __uint_as_float(smA[lr1 * LDA + c + 1]);
            d0 = fmaf(acc[nt][0], v00, fmaf(acc[nt][1], v01, d0));
            d1 = fmaf(acc[nt][2], v10, fmaf(acc[nt][3], v11, d1));
        }
    }
    d0 += __shfl_xor_sync(0xffffffffu, d0, 1);
    d0 += __shfl_xor_sync(0xffffffffu, d0, 2);
    d1 += __shfl_xor_sync(0xffffffffu, d1, 1);
    d1 += __shfl_xor_sync(0xffffffffu, d1, 2);
    if (tig == 0) {
        sPart[nh][mt][gid] = d0;
        sPart[nh][mt][gid + 8] = d1;
    }
    __syncthreads();

    if (t < 64) {
        int mtt = t >> 4, r = t & 15;
        int gr = row0 + mtt * 16 + r;
        if (gr < R) rowdot[gr] = sPart[0][mtt][r] + sPart[1][mtt][r];
    }
}

// ---------------- K5: broadcast scalar add (float4) ----------------
__global__ void k_final(float* __restrict__ out)
{
    int idx4 = blockIdx.x * blockDim.x + threadIdx.x;
    if (idx4 >= NATOM * FD / 4) return;
    int n = idx4 >> 5;
    float s = g_rowp[n * 3 + 0] + g_rowp[n * 3 + 1] + g_rowp[n * 3 + 2]
            + g_rowd[n * 5 + 0] + g_rowd[n * 5 + 1] + g_rowd[n * 5 + 2]
            + g_rowd[n * 5 + 3] + g_rowd[n * 5 + 4];
    float4 o = ((float4*)out)[idx4];
    o.x += s; o.y += s; o.z += s; o.w += s;
    ((float4*)out)[idx4] = o;
}

// ---------------- launch ----------------
extern "C" void kernel_launch(void* const* d_in, const int* in_sizes, int n_in,
                              void* d_out, int out_size)
{
    const float* atom = (const float*)d_in[0];
    const int*   nbr  = (const int*)d_in[1];
    const float* gs   = (const float*)d_in[2];
    const float* gp   = (const float*)d_in[3];
    const float* gd   = (const float*)d_in[4];
    const float* Gs   = (const float*)d_in[5];
    const float* Gp   = (const float*)d_in[6];
    const float* Gd   = (const float*)d_in[7];
    const float* P1   = (const float*)d_in[8];
    const float* P2   = (const float*)d_in[9];
    const float* D1   = (const float*)d_in[10];
    const float* D2   = (const float*)d_in[11];
    float* out = (float*)d_out;

    MlpArgs a;
    for (int ch = 0; ch < 4; ch++) {
        a.wr[ch] = (const float*)d_in[12 + ch * 4 + 0];
        a.br[ch] = (const float*)d_in[12 + ch * 4 + 1];
        a.w1[ch] = (const float*)d_in[12 + ch * 4 + 2];
        a.b1[ch] = (const float*)d_in[12 + ch * 4 + 3];
    }

    k_mmt<<<dim3(16, 2), 128>>>(P1, P2, D1, D2);
    k_resmlp_mma<<<dim3((NATOM + 63) / 64, 4), 256>>>(atom, a, out);
    k_env_mma<<<740, 128>>>(nbr, gs, gp, gd, Gs, Gp, Gd, out);
    k_quad_mma<<<NP_BLK + ND_BLK, 256>>>();
    k_final<<<(NATOM * FD / 4 + 255) / 256, 256>>>(out);
}

// round 13
// speedup vs baseline: 1.0015x; 1.0015x over previous
#include <cuda_runtime.h>

#define NATOM 30000
#define NNJ 12
#define KD 32
#define FD 128
#define LDA 132

// sB layout: [32 k][152 cols]; cols: s [0,16), p a*16+[16,64), d a*16+[64,144), pads zeroed
#define LDB 152
#define SB_FLOATS (32 * LDB)           // 4864
#define FEA_LD 17
#define SFEA_FLOATS (3 * 128 * FEA_LD) // 6528

#define NP_BLK 1407   // ceil(30000*3/64)
#define ND_BLK 2344   // ceil(30000*5/64)

// ---------------- device scratch ----------------
__device__ float g_sfea[NATOM * FD];
__device__ float g_pfea[NATOM * FD];
__device__ float g_dfea[NATOM * FD];
__device__ float g_allp[NATOM * 3 * FD];   // [n][a][f]
__device__ float g_alld[NATOM * 5 * FD];   // [n][a][f]
__device__ float g_Mp[FD * FD];            // P1 @ P2^T
__device__ float g_Md[FD * FD];            // D1 @ D2^T
__device__ float g_rowp[NATOM * 3];
__device__ float g_rowd[NATOM * 5];

__device__ __forceinline__ float siluf(float x) {
    return x / (1.0f + __expf(-x));
}

__device__ __forceinline__ unsigned tf32r(float x) {
    unsigned u;
    asm("cvt.rna.tf32.f32 %0, %1;" : "=r"(u) : "f"(x));
    return u;
}

__device__ __forceinline__ void mma_tf32(float c[4], const unsigned a[4],
                                         unsigned b0, unsigned b1) {
    asm volatile(
        "mma.sync.aligned.m16n8k8.row.col.f32.tf32.tf32.f32 "
        "{%0,%1,%2,%3},{%4,%5,%6,%7},{%8,%9},{%0,%1,%2,%3};"
        : "+f"(c[0]), "+f"(c[1]), "+f"(c[2]), "+f"(c[3])
        : "r"(a[0]), "r"(a[1]), "r"(a[2]), "r"(a[3]), "r"(b0), "r"(b1));
}

// ---------------- K1: Mp = P1 @ P2^T, Md = D1 @ D2^T ----------------
__global__ __launch_bounds__(128)
void k_mmt(const float* __restrict__ P1, const float* __restrict__ P2,
           const float* __restrict__ D1, const float* __restrict__ D2)
{
    const float* A = blockIdx.y ? D1 : P1;
    const float* B = blockIdx.y ? D2 : P2;
    float* M = blockIdx.y ? g_Md : g_Mp;

    __shared__ float smA[8 * FD];
    __shared__ float smB[16 * LDA];
    int t = threadIdx.x;
    int i0 = blockIdx.x * 8;

#pragma unroll
    for (int r = 0; r < 2; r++) {
        int e = t + r * 128;
        ((float4*)smA)[e] = ((const float4*)A)[i0 * 32 + e];
    }

    float acc[8];
#pragma unroll
    for (int i = 0; i < 8; i++) acc[i] = 0.f;

    for (int g0 = 0; g0 < FD; g0 += 16) {
        __syncthreads();
#pragma unroll
        for (int r = 0; r < 4; r++) {
            int e = t + r * 128;
            int j = e >> 2, q = e & 3;
            float4 v = ((const float4*)B)[j * 32 + (g0 >> 2) + q];
            smB[(q * 4 + 0) * LDA + j] = v.x;
            smB[(q * 4 + 1) * LDA + j] = v.y;
            smB[(q * 4 + 2) * LDA + j] = v.z;
            smB[(q * 4 + 3) * LDA + j] = v.w;
        }
        __syncthreads();
#pragma unroll
        for (int gl = 0; gl < 16; gl++) {
            float b = smB[gl * LDA + t];
#pragma unroll
            for (int i = 0; i < 8; i++)
                acc[i] = fmaf(smA[i * FD + g0 + gl], b, acc[i]);
        }
    }
#pragma unroll
    for (int i = 0; i < 8; i++) M[(i0 + i) * FD + t] = acc[i];
}

// ---------------- K2: fused ResMLP via tf32 mma, smem-staged W (16-wide) ----------------
struct MlpArgs {
    const float* wr[4]; const float* br[4];
    const float* w1[4]; const float* b1[4];
};

__device__ __forceinline__ void mma_gemm_pass(const float* __restrict__ W,
                                              float acc[8][4],
                                              const unsigned* smA, unsigned* smW,
                                              int t, int mt, int nh, int gid, int tig)
{
#pragma unroll
    for (int nt = 0; nt < 8; nt++)
#pragma unroll
        for (int c = 0; c < 4; c++) acc[nt][c] = 0.f;

    int wrow = t >> 1, wq = (t & 1) * 8;
    int r0 = mt * 16 + gid;

    for (int k0 = 0; k0 < FD; k0 += 16) {
        __syncthreads();          // smW reuse from previous slice
        float4 v0 = *(const float4*)&W[wrow * FD + k0 + wq];
        float4 v1 = *(const float4*)&W[wrow * FD + k0 + wq + 4];
        smW[(wq + 0) * 132 + wrow] = tf32r(v0.x);
        smW[(wq + 1) * 132 + wrow] = tf32r(v0.y);
        smW[(wq + 2) * 132 + wrow] = tf32r(v0.z);
        smW[(wq + 3) * 132 + wrow] = tf32r(v0.w);
        smW[(wq + 4) * 132 + wrow] = tf32r(v1.x);
        smW[(wq + 5) * 132 + wrow] = tf32r(v1.y);
        smW[(wq + 6) * 132 + wrow] = tf32r(v1.z);
        smW[(wq + 7) * 132 + wrow] = tf32r(v1.w);
        __syncthreads();

#pragma unroll
        for (int kk = 0; kk < 16; kk += 8) {
            unsigned a[4];
            a[0] = smA[r0 * LDA + k0 + kk + tig];
            a[1] = smA[(r0 + 8) * LDA + k0 + kk + tig];
            a[2] = smA[r0 * LDA + k0 + kk + tig + 4];
            a[3] = smA[(r0 + 8) * LDA + k0 + kk + tig + 4];
#pragma unroll
            for (int nt = 0; nt < 8; nt++) {
                int n0 = nh * 64 + nt * 8;
                unsigned b0 = smW[(kk + tig) * 132 + n0 + gid];
                unsigned b1 = smW[(kk + tig + 4) * 132 + n0 + gid];
                mma_tf32(acc[nt], a, b0, b1);
            }
        }
    }
    __syncthreads();
}

__global__ __launch_bounds__(256)
void k_resmlp_mma(const float* __restrict__ x, MlpArgs args, float* __restrict__ out)
{
    __shared__ unsigned smA[64 * LDA];
    __shared__ unsigned smW[16 * 132];

    int ch = blockIdx.y;
    const float* wr = args.wr[ch];
    const float* brp = args.br[ch];
    const float* w1 = args.w1[ch];
    const float* b1p = args.b1[ch];
    float* dst = (ch == 0) ? out : (ch == 1) ? g_sfea : (ch == 2) ? g_pfea : g_dfea;

    int row0 = blockIdx.x * 64;
    int t = threadIdx.x;
    int w = t >> 5, lane = t & 31;
    int mt = w & 3, nh = w >> 2;
    int gid = lane >> 2, tig = lane & 3;

#pragma unroll
    for (int r = 0; r < 8; r++) {
        int e = t + r * 256;
        int m = e >> 5, c4 = e & 31;
        int gr = row0 + m;
        float4 v = make_float4(0.f, 0.f, 0.f, 0.f);
        if (gr < NATOM) v = ((const float4*)x)[gr * 32 + c4];
        smA[m * LDA + c4 * 4 + 0] = tf32r(siluf(v.x));
        smA[m * LDA + c4 * 4 + 1] = tf32r(siluf(v.y));
        smA[m * LDA + c4 * 4 + 2] = tf32r(siluf(v.z));
        smA[m * LDA + c4 * 4 + 3] = tf32r(siluf(v.w));
    }

    float acc[8][4];
    mma_gemm_pass(wr, acc, smA, smW, t, mt, nh, gid, tig);

    {
        int r0 = row0 + mt * 16 + gid;
        int r1 = r0 + 8;
#pragma unroll
        for (int nt = 0; nt < 8; nt++) {
            int c = nh * 64 + nt * 8 + 2 * tig;
            float2 br2 = *(const float2*)&brp[c];
            float2 x0 = make_float2(0.f, 0.f), x1 = x0;
            if (r0 < NATOM) x0 = *(const float2*)&x[r0 * FD + c];
            if (r1 < NATOM) x1 = *(const float2*)&x[r1 * FD + c];
            int lr0 = mt * 16 + gid, lr1 = lr0 + 8;
            smA[lr0 * LDA + c]     = tf32r(siluf(acc[nt][0] + x0.x + br2.x));
            smA[lr0 * LDA + c + 1] = tf32r(siluf(acc[nt][1] + x0.y + br2.y));
            smA[lr1 * LDA + c]     = tf32r(siluf(acc[nt][2] + x1.x + br2.x));
            smA[lr1 * LDA + c + 1] = tf32r(siluf(acc[nt][3] + x1.y + br2.y));
        }
    }

    mma_gemm_pass(w1, acc, smA, smW, t, mt, nh, gid, tig);

    {
        int r0 = row0 + mt * 16 + gid;
        int r1 = r0 + 8;
#pragma unroll
        for (int nt = 0; nt < 8; nt++) {
            int c = nh * 64 + nt * 8 + 2 * tig;
            float2 b2 = *(const float2*)&b1p[c];
            if (r0 < NATOM)
                *(float2*)&dst[r0 * FD + c] =
                    make_float2(acc[nt][0] + b2.x, acc[nt][1] + b2.y);
            if (r1 < NATOM)
                *(float2*)&dst[r1 * FD + c] =
                    make_float2(acc[nt][2] + b2.x, acc[nt][3] + b2.y);
        }
    }
}

// ---------------- K3: env via tf32 mma, software-pipelined ----------------
__global__ __launch_bounds__(128)
void k_env_mma(const int* __restrict__ nbr,
               const float* __restrict__ gs, const float* __restrict__ gp,
               const float* __restrict__ gd,
               const float* __restrict__ Gs, const float* __restrict__ Gp,
               const float* __restrict__ Gd,
               float* __restrict__ out)
{
    __shared__ unsigned sBu[SB_FLOATS];
    __shared__ float sFea[SFEA_FLOATS];

    int t = threadIdx.x;
    int w = t >> 5;
    int lane = t & 31;
    int gid = lane >> 2;
    int tig = lane & 3;

    // zero once: covers all pad columns / pad j entries (never overwritten later)
    for (int e = t; e < SB_FLOATS; e += 128) sBu[e] = 0u;
    for (int e = t; e < SFEA_FLOATS; e += 128) sFea[e] = 0.f;

    const float4* gs4 = (const float4*)gs;
    const float4* gp4 = (const float4*)gp;
    const float4* gd4 = (const float4*)gd;

    // ---- prologue prefetch (registers) ----
    int n = blockIdx.x;
    int4 jA, jB, jC;
    float4 pgs, pgp[3], pgd[4];
    {
        const int4* nb4 = (const int4*)(nbr + n * NNJ);
        jA = nb4[0]; jB = nb4[1]; jC = nb4[2];
        if (t < 96) pgs = gs4[(size_t)n * 96 + t];
#pragma unroll
        for (int r = 0; r < 3; r++) {
            int e = t + r * 128;
            if (e < 288) pgp[r] = gp4[(size_t)n * 288 + e];
        }
#pragma unroll
        for (int r = 0; r < 4; r++) {
            int e = t + r * 128;
            if (e < 480) pgd[r] = gd4[(size_t)n * 480 + e];
        }
    }

    for (; n < NATOM; n += gridDim.x) {
        int jn[NNJ] = {jA.x, jA.y, jA.z, jA.w, jB.x, jB.y, jB.z, jB.w,
                       jC.x, jC.y, jC.z, jC.w};

        // fea gathers first (longest-latency loads of the stage phase)
        {
            float* r0 = sFea + t * FEA_LD;
            float* r1 = sFea + 128 * FEA_LD + t * FEA_LD;
            float* r2 = sFea + 256 * FEA_LD + t * FEA_LD;
#pragma unroll
            for (int j = 0; j < NNJ; j++) {
                size_t off = (size_t)jn[j] * FD + t;
                r0[j] = g_sfea[off];
                r1[j] = g_pfea[off];
                r2[j] = g_dfea[off];
            }
        }
        // gs from regs
        if (t < 96) {
            int j = t >> 3, q = t & 7;
            int base = (q * 4) * LDB + j;
            sBu[base]           = tf32r(pgs.x);
            sBu[base + LDB]     = tf32r(pgs.y);
            sBu[base + 2 * LDB] = tf32r(pgs.z);
            sBu[base + 3 * LDB] = tf32r(pgs.w);
        }
        // gp from regs
#pragma unroll
        for (int r = 0; r < 3; r++) {
            int e = t + r * 128;
            if (e < 288) {
                float vv[4] = {pgp[r].x, pgp[r].y, pgp[r].z, pgp[r].w};
#pragma unroll
                for (int u = 0; u < 4; u++) {
                    int idx = e * 4 + u;
                    int j = idx / 96, rr = idx % 96;
                    int k = rr / 3, a = rr % 3;
                    sBu[k * LDB + 16 + a * 16 + j] = tf32r(vv[u]);
                }
            }
        }
        // gd from regs
#pragma unroll
        for (int r = 0; r < 4; r++) {
            int e = t + r * 128;
            if (e < 480) {
                float vv[4] = {pgd[r].x, pgd[r].y, pgd[r].z, pgd[r].w};
#pragma unroll
                for (int u = 0; u < 4; u++) {
                    int idx = e * 4 + u;
                    int j = idx / 160, rr = idx % 160;
                    int k = rr / 5, a = rr % 5;
                    sBu[k * LDB + 64 + a * 16 + j] = tf32r(vv[u]);
                }
            }
        }
        __syncthreads();

        // ---- prefetch next atom during compute ----
        int nn = n + gridDim.x;
        if (nn < NATOM) {
            const int4* nb4 = (const int4*)(nbr + nn * NNJ);
            jA = nb4[0]; jB = nb4[1]; jC = nb4[2];
            if (t < 96) pgs = gs4[(size_t)nn * 96 + t];
#pragma unroll
            for (int r = 0; r < 3; r++) {
                int e = t + r * 128;
                if (e < 288) pgp[r] = gp4[(size_t)nn * 288 + e];
            }
#pragma unroll
            for (int r = 0; r < 4; r++) {
                int e = t + r * 128;
                if (e < 480) pgd[r] = gd4[(size_t)nn * 480 + e];
            }
        }

        // ---- compute: per-channel A reload (G is L1-hot) ----
        const float* Gtab[3] = {Gs, Gp, Gd};
#pragma unroll
        for (int ch = 0; ch < 3; ch++) {
            const float* G = Gtab[ch];
            unsigned Ac[2][4][4];
#pragma unroll
            for (int mt = 0; mt < 2; mt++) {
#pragma unroll
                for (int k4 = 0; k4 < 4; k4++) {
                    int r0 = w * 32 + mt * 16 + gid;
                    int c0 = k4 * 8 + tig;
                    Ac[mt][k4][0] = tf32r(G[r0 * 32 + c0]);
                    Ac[mt][k4][1] = tf32r(G[(r0 + 8) * 32 + c0]);
                    Ac[mt][k4][2] = tf32r(G[r0 * 32 + c0 + 4]);
                    Ac[mt][k4][3] = tf32r(G[(r0 + 8) * 32 + c0 + 4]);
                }
            }
            const int NA = (ch == 0) ? 1 : (ch == 1) ? 3 : 5;
            const int CB = (ch == 0) ? 0 : (ch == 1) ? 16 : 64;
            const float* fbase = sFea + ch * (128 * FEA_LD);
#pragma unroll
            for (int a = 0; a < NA; a++) {
                float Pl[2][2] = {{0.f, 0.f}, {0.f, 0.f}};
#pragma unroll
                for (int half = 0; half < 2; half++) {
                    int cb = CB + a * 16 + half * 8;
                    unsigned bf[8];
#pragma unroll
                    for (int k4 = 0; k4 < 4; k4++) {
                        bf[2 * k4]     = sBu[(k4 * 8 + tig) * LDB + cb + gid];
                        bf[2 * k4 + 1] = sBu[(k4 * 8 + tig + 4) * LDB + cb + gid];
                    }
                    int j0 = half * 8 + 2 * tig;
#pragma unroll
                    for (int mt = 0; mt < 2; mt++) {
                        float C[4] = {0.f, 0.f, 0.f, 0.f};
#pragma unroll
                        for (int k4 = 0; k4 < 4; k4++)
                            mma_tf32(C, Ac[mt][k4], bf[2 * k4], bf[2 * k4 + 1]);
                        int r = w * 32 + mt * 16 + gid;
                        const float* fr0 = fbase + r * FEA_LD;
                        const float* fr1 = fr0 + 8 * FEA_LD;
                        Pl[mt][0] += C[0] * fr0[j0] + C[1] * fr0[j0 + 1];
                        Pl[mt][1] += C[2] * fr1[j0] + C[3] * fr1[j0 + 1];
                    }
                }
                // reduce + store this (ch, a)
#pragma unroll
                for (int mt = 0; mt < 2; mt++) {
#pragma unroll
                    for (int rr = 0; rr < 2; rr++) {
                        float v = Pl[mt][rr];
                        v += __shfl_xor_sync(0xffffffffu, v, 1);
                        v += __shfl_xor_sync(0xffffffffu, v, 2);
                        if (tig == 0) {
                            int r = w * 32 + mt * 16 + rr * 8 + gid;
                            if (ch == 0)
                                out[(size_t)n * FD + r] += v;
                            else if (ch == 1)
                                g_allp[((size_t)n * 3 + a) * FD + r] = v;
                            else
                                g_alld[((size_t)n * 5 + a) * FD + r] = v;
                        }
                    }
                }
            }
        }

        __syncthreads();
    }
}

// ---------------- K4: rowdot[r] = v_r . (M v_r), merged p+d, smem-staged M ----------------
__global__ __launch_bounds__(256)
void k_quad_mma()
{
    int bid = blockIdx.x;
    int which = (bid >= NP_BLK) ? 1 : 0;
    const float* V = which ? g_alld : g_allp;
    const float* M = which ? g_Md : g_Mp;
    float* rowdot = which ? g_rowd : g_rowp;
    int R = which ? NATOM * 5 : NATOM * 3;
    int row0 = (which ? bid - NP_BLK : bid) * 64;

    __shared__ unsigned smA[64 * LDA];
    __shared__ unsigned smW[16 * 132];
    __shared__ float sPart[2][4][16];

    int t = threadIdx.x;
    int w = t >> 5, lane = t & 31;
    int mt = w & 3, nh = w >> 2;
    int gid = lane >> 2, tig = lane & 3;

#pragma unroll
    for (int r = 0; r < 8; r++) {
        int e = t + r * 256;
        int m = e >> 5, c4 = e & 31;
        int gr = row0 + m;
        float4 v = make_float4(0.f, 0.f, 0.f, 0.f);
        if (gr < R) v = ((const float4*)V)[gr * 32 + c4];
        smA[m * LDA + c4 * 4 + 0] = tf32r(v.x);
        smA[m * LDA + c4 * 4 + 1] = tf32r(v.y);
        smA[m * LDA + c4 * 4 + 2] = tf32r(v.z);
        smA[m * LDA + c4 * 4 + 3] = tf32r(v.w);
    }

    float acc[8][4];
#pragma unroll
    for (int nt = 0; nt < 8; nt++)
#pragma unroll
        for (int c = 0; c < 4; c++) acc[nt][c] = 0.f;

    int kr = t >> 4, c8 = (t & 15) * 8;
    int r0 = mt * 16 + gid;

    for (int k0 = 0; k0 < FD; k0 += 16) {
        __syncthreads();
        float4 v0 = *(const float4*)&M[(k0 + kr) * FD + c8];
        float4 v1 = *(const float4*)&M[(k0 + kr) * FD + c8 + 4];
        smW[kr * 132 + c8 + 0] = tf32r(v0.x);
        smW[kr * 132 + c8 + 1] = tf32r(v0.y);
        smW[kr * 132 + c8 + 2] = tf32r(v0.z);
        smW[kr * 132 + c8 + 3] = tf32r(v0.w);
        smW[kr * 132 + c8 + 4] = tf32r(v1.x);
        smW[kr * 132 + c8 + 5] = tf32r(v1.y);
        smW[kr * 132 + c8 + 6] = tf32r(v1.z);
        smW[kr * 132 + c8 + 7] = tf32r(v1.w);
        __syncthreads();

#pragma unroll
        for (int kk = 0; kk < 16; kk += 8) {
            unsigned a[4];
            a[0] = smA[r0 * LDA + k0 + kk + tig];
            a[1] = smA[(r0 + 8) * LDA + k0 + kk + tig];
            a[2] = smA[r0 * LDA + k0 + kk + tig + 4];
            a[3] = smA[(r0 + 8) * LDA + k0 + kk + tig + 4];
#pragma unroll
            for (int nt = 0; nt < 8; nt++) {
                int n0 = nh * 64 + nt * 8;
                unsigned b0 = smW[(kk + tig) * 132 + n0 + gid];
                unsigned b1 = smW[(kk + tig + 4) * 132 + n0 + gid];
                mma_tf32(acc[nt], a, b0, b1);
            }
        }
    }

    // fused row dot vs smem V (tf32-truncated)
    float d0 = 0.f, d1 = 0.f;
    {
        int lr0 = mt * 16 + gid, lr1 = lr0 + 8;
#pragma unroll
        for (int nt = 0; nt < 8; nt++) {
            int c = nh * 64 + nt * 8 + 2 * tig;
            float v00 = __uint_as_float(smA[lr0 * LDA + c]);
            float v01 = __uint_as_float(smA[lr0 * LDA + c + 1]);
            float v10 = __uint_as_float(smA[lr1 * LDA + c]);
            float v11 = __uint_as_float(smA[lr1 * LDA + c + 1]);
            d0 = fmaf(acc[nt][0], v00, fmaf(acc[nt][1], v01, d0));
            d1 = fmaf(acc[nt][2], v10, fmaf(acc[nt][3], v11, d1));
        }
    }
    d0 += __shfl_xor_sync(0xffffffffu, d0, 1);
    d0 += __shfl_xor_sync(0xffffffffu, d0, 2);
    d1 += __shfl_xor_sync(0xffffffffu, d1, 1);
    d1 += __shfl_xor_sync(0xffffffffu, d1, 2);
    if (tig == 0) {
        sPart[nh][mt][gid] = d0;
        sPart[nh][mt][gid + 8] = d1;
    }
    __syncthreads();

    if (t < 64) {
        int mtt = t >> 4, r = t & 15;
        int gr = row0 + mtt * 16 + r;
        if (gr < R) rowdot[gr] = sPart[0][mtt][r] + sPart[1][mtt][r];
    }
}

// ---------------- K5: broadcast scalar add (float4) ----------------
__global__ void k_final(float* __restrict__ out)
{
    int idx4 = blockIdx.x * blockDim.x + threadIdx.x;
    if (idx4 >= NATOM * FD / 4) return;
    int n = idx4 >> 5;
    float s = g_rowp[n * 3 + 0] + g_rowp[n * 3 + 1] + g_rowp[n * 3 + 2]
            + g_rowd[n * 5 + 0] + g_rowd[n * 5 + 1] + g_rowd[n * 5 + 2]
            + g_rowd[n * 5 + 3] + g_rowd[n * 5 + 4];
    float4 o = ((float4*)out)[idx4];
    o.x += s; o.y += s; o.z += s; o.w += s;
    ((float4*)out)[idx4] = o;
}

// ---------------- launch ----------------
extern "C" void kernel_launch(void* const* d_in, const int* in_sizes, int n_in,
                              void* d_out, int out_size)
{
    const float* atom = (const float*)d_in[0];
    const int*   nbr  = (const int*)d_in[1];
    const float* gs   = (const float*)d_in[2];
    const float* gp   = (const float*)d_in[3];
    const float* gd   = (const float*)d_in[4];
    const float* Gs   = (const float*)d_in[5];
    const float* Gp   = (const float*)d_in[6];
    const float* Gd   = (const float*)d_in[7];
    const float* P1   = (const float*)d_in[8];
    const float* P2   = (const float*)d_in[9];
    const float* D1   = (const float*)d_in[10];
    const float* D2   = (const float*)d_in[11];
    float* out = (float*)d_out;

    MlpArgs a;
    for (int ch = 0; ch < 4; ch++) {
        a.wr[ch] = (const float*)d_in[12 + ch * 4 + 0];
        a.br[ch] = (const float*)d_in[12 + ch * 4 + 1];
        a.w1[ch] = (const float*)d_in[12 + ch * 4 + 2];
        a.b1[ch] = (const float*)d_in[12 + ch * 4 + 3];
    }

    k_mmt<<<dim3(16, 2), 128>>>(P1, P2, D1, D2);
    k_resmlp_mma<<<dim3((NATOM + 63) / 64, 4), 256>>>(atom, a, out);
    k_env_mma<<<740, 128>>>(nbr, gs, gp, gd, Gs, Gp, Gd, out);
    k_quad_mma<<<NP_BLK + ND_BLK, 256>>>();
    k_final<<<(NATOM * FD / 4 + 255) / 256, 256>>>(out);
}

// round 14
// speedup vs baseline: 1.1071x; 1.1055x over previous
#include <cuda_runtime.h>

#define NATOM 30000
#define NNJ 12
#define KD 32
#define FD 128
#define LDA 132

// sB layout: [32 k][152 cols]; cols: s [0,16), p a*16+[16,64), d a*16+[64,144), pads zeroed
#define LDB 152
#define SB_FLOATS (32 * LDB)           // 4864
#define FEA_LD 17
#define SFEA_FLOATS (3 * 128 * FEA_LD) // 6528

#define NP_BLK 1407   // ceil(30000*3/64)
#define ND_BLK 2344   // ceil(30000*5/64)

// ---------------- device scratch ----------------
__device__ float g_sfea[NATOM * FD];
__device__ float g_pfea[NATOM * FD];
__device__ float g_dfea[NATOM * FD];
__device__ float g_allp[NATOM * 3 * FD];   // [n][a][f]
__device__ float g_alld[NATOM * 5 * FD];   // [n][a][f]
__device__ float g_Mp[FD * FD];            // P1 @ P2^T
__device__ float g_Md[FD * FD];            // D1 @ D2^T
__device__ float g_rowp[NATOM * 3];
__device__ float g_rowd[NATOM * 5];

__device__ __forceinline__ float siluf(float x) {
    return x / (1.0f + __expf(-x));
}

__device__ __forceinline__ unsigned tf32r(float x) {
    unsigned u;
    asm("cvt.rna.tf32.f32 %0, %1;" : "=r"(u) : "f"(x));
    return u;
}

__device__ __forceinline__ void mma_tf32(float c[4], const unsigned a[4],
                                         unsigned b0, unsigned b1) {
    asm volatile(
        "mma.sync.aligned.m16n8k8.row.col.f32.tf32.tf32.f32 "
        "{%0,%1,%2,%3},{%4,%5,%6,%7},{%8,%9},{%0,%1,%2,%3};"
        : "+f"(c[0]), "+f"(c[1]), "+f"(c[2]), "+f"(c[3])
        : "r"(a[0]), "r"(a[1]), "r"(a[2]), "r"(a[3]), "r"(b0), "r"(b1));
}

// ---------------- K1: Mp = P1 @ P2^T, Md = D1 @ D2^T ----------------
__global__ __launch_bounds__(128)
void k_mmt(const float* __restrict__ P1, const float* __restrict__ P2,
           const float* __restrict__ D1, const float* __restrict__ D2)
{
    const float* A = blockIdx.y ? D1 : P1;
    const float* B = blockIdx.y ? D2 : P2;
    float* M = blockIdx.y ? g_Md : g_Mp;

    __shared__ float smA[8 * FD];
    __shared__ float smB[16 * LDA];
    int t = threadIdx.x;
    int i0 = blockIdx.x * 8;

#pragma unroll
    for (int r = 0; r < 2; r++) {
        int e = t + r * 128;
        ((float4*)smA)[e] = ((const float4*)A)[i0 * 32 + e];
    }

    float acc[8];
#pragma unroll
    for (int i = 0; i < 8; i++) acc[i] = 0.f;

    for (int g0 = 0; g0 < FD; g0 += 16) {
        __syncthreads();
#pragma unroll
        for (int r = 0; r < 4; r++) {
            int e = t + r * 128;
            int j = e >> 2, q = e & 3;
            float4 v = ((const float4*)B)[j * 32 + (g0 >> 2) + q];
            smB[(q * 4 + 0) * LDA + j] = v.x;
            smB[(q * 4 + 1) * LDA + j] = v.y;
            smB[(q * 4 + 2) * LDA + j] = v.z;
            smB[(q * 4 + 3) * LDA + j] = v.w;
        }
        __syncthreads();
#pragma unroll
        for (int gl = 0; gl < 16; gl++) {
            float b = smB[gl * LDA + t];
#pragma unroll
            for (int i = 0; i < 8; i++)
                acc[i] = fmaf(smA[i * FD + g0 + gl], b, acc[i]);
        }
    }
#pragma unroll
    for (int i = 0; i < 8; i++) M[(i0 + i) * FD + t] = acc[i];
}

// ---------------- K2: fused ResMLP via tf32 mma, reg-prefetched W staging ----------------
struct MlpArgs {
    const float* wr[4]; const float* br[4];
    const float* w1[4]; const float* b1[4];
};

__device__ __forceinline__ void mma_gemm_pass(const float* __restrict__ W,
                                              float acc[8][4],
                                              const unsigned* smA, unsigned* smW,
                                              int t, int mt, int nh, int gid, int tig)
{
#pragma unroll
    for (int nt = 0; nt < 8; nt++)
#pragma unroll
        for (int c = 0; c < 4; c++) acc[nt][c] = 0.f;

    int wrow = t >> 1, wq = (t & 1) * 8;
    int r0 = mt * 16 + gid;
    const float* wptr = W + wrow * FD + wq;

    // preload slice 0 into registers
    float4 va = *(const float4*)(wptr);
    float4 vb = *(const float4*)(wptr + 4);

    for (int s = 0; s < 8; s++) {
        int k0 = s * 16;
        __syncthreads();          // smW free (readers of previous slice done)
        smW[(wq + 0) * 132 + wrow] = tf32r(va.x);
        smW[(wq + 1) * 132 + wrow] = tf32r(va.y);
        smW[(wq + 2) * 132 + wrow] = tf32r(va.z);
        smW[(wq + 3) * 132 + wrow] = tf32r(va.w);
        smW[(wq + 4) * 132 + wrow] = tf32r(vb.x);
        smW[(wq + 5) * 132 + wrow] = tf32r(vb.y);
        smW[(wq + 6) * 132 + wrow] = tf32r(vb.z);
        smW[(wq + 7) * 132 + wrow] = tf32r(vb.w);
        // prefetch next slice during this slice's compute
        if (s < 7) {
            va = *(const float4*)(wptr + (s + 1) * 16);
            vb = *(const float4*)(wptr + (s + 1) * 16 + 4);
        }
        __syncthreads();

#pragma unroll
        for (int kk = 0; kk < 16; kk += 8) {
            unsigned a[4];
            a[0] = smA[r0 * LDA + k0 + kk + tig];
            a[1] = smA[(r0 + 8) * LDA + k0 + kk + tig];
            a[2] = smA[r0 * LDA + k0 + kk + tig + 4];
            a[3] = smA[(r0 + 8) * LDA + k0 + kk + tig + 4];
#pragma unroll
            for (int nt = 0; nt < 8; nt++) {
                int n0 = nh * 64 + nt * 8;
                unsigned b0 = smW[(kk + tig) * 132 + n0 + gid];
                unsigned b1 = smW[(kk + tig + 4) * 132 + n0 + gid];
                mma_tf32(acc[nt], a, b0, b1);
            }
        }
    }
    __syncthreads();   // everyone done with smA/smW before caller's epilogue
}

__global__ __launch_bounds__(256)
void k_resmlp_mma(const float* __restrict__ x, MlpArgs args, float* __restrict__ out)
{
    __shared__ unsigned smA[64 * LDA];
    __shared__ unsigned smW[16 * 132];

    int ch = blockIdx.y;
    const float* wr = args.wr[ch];
    const float* brp = args.br[ch];
    const float* w1 = args.w1[ch];
    const float* b1p = args.b1[ch];
    float* dst = (ch == 0) ? out : (ch == 1) ? g_sfea : (ch == 2) ? g_pfea : g_dfea;

    int row0 = blockIdx.x * 64;
    int t = threadIdx.x;
    int w = t >> 5, lane = t & 31;
    int mt = w & 3, nh = w >> 2;
    int gid = lane >> 2, tig = lane & 3;

#pragma unroll
    for (int r = 0; r < 8; r++) {
        int e = t + r * 256;
        int m = e >> 5, c4 = e & 31;
        int gr = row0 + m;
        float4 v = make_float4(0.f, 0.f, 0.f, 0.f);
        if (gr < NATOM) v = ((const float4*)x)[gr * 32 + c4];
        smA[m * LDA + c4 * 4 + 0] = tf32r(siluf(v.x));
        smA[m * LDA + c4 * 4 + 1] = tf32r(siluf(v.y));
        smA[m * LDA + c4 * 4 + 2] = tf32r(siluf(v.z));
        smA[m * LDA + c4 * 4 + 3] = tf32r(siluf(v.w));
    }

    float acc[8][4];
    mma_gemm_pass(wr, acc, smA, smW, t, mt, nh, gid, tig);

    {
        int r0 = row0 + mt * 16 + gid;
        int r1 = r0 + 8;
#pragma unroll
        for (int nt = 0; nt < 8; nt++) {
            int c = nh * 64 + nt * 8 + 2 * tig;
            float2 br2 = *(const float2*)&brp[c];
            float2 x0 = make_float2(0.f, 0.f), x1 = x0;
            if (r0 < NATOM) x0 = *(const float2*)&x[r0 * FD + c];
            if (r1 < NATOM) x1 = *(const float2*)&x[r1 * FD + c];
            int lr0 = mt * 16 + gid, lr1 = lr0 + 8;
            smA[lr0 * LDA + c]     = tf32r(siluf(acc[nt][0] + x0.x + br2.x));
            smA[lr0 * LDA + c + 1] = tf32r(siluf(acc[nt][1] + x0.y + br2.y));
            smA[lr1 * LDA + c]     = tf32r(siluf(acc[nt][2] + x1.x + br2.x));
            smA[lr1 * LDA + c + 1] = tf32r(siluf(acc[nt][3] + x1.y + br2.y));
        }
    }

    mma_gemm_pass(w1, acc, smA, smW, t, mt, nh, gid, tig);

    {
        int r0 = row0 + mt * 16 + gid;
        int r1 = r0 + 8;
#pragma unroll
        for (int nt = 0; nt < 8; nt++) {
            int c = nh * 64 + nt * 8 + 2 * tig;
            float2 b2 = *(const float2*)&b1p[c];
            if (r0 < NATOM)
                *(float2*)&dst[r0 * FD + c] =
                    make_float2(acc[nt][0] + b2.x, acc[nt][1] + b2.y);
            if (r1 < NATOM)
                *(float2*)&dst[r1 * FD + c] =
                    make_float2(acc[nt][2] + b2.x, acc[nt][3] + b2.y);
        }
    }
}

// ---------------- K3: env via tf32 mma (R7-passing version, grid 740) ----------------
__global__ __launch_bounds__(128)
void k_env_mma(const int* __restrict__ nbr,
               const float* __restrict__ gs, const float* __restrict__ gp,
               const float* __restrict__ gd,
               const float* __restrict__ Gs, const float* __restrict__ Gp,
               const float* __restrict__ Gd,
               float* __restrict__ out)
{
    __shared__ unsigned sBu[SB_FLOATS];
    __shared__ float sFea[SFEA_FLOATS];

    int t = threadIdx.x;
    int w = t >> 5;
    int lane = t & 31;
    int gid = lane >> 2;
    int tig = lane & 3;

    const float* Gtab[3] = {Gs, Gp, Gd};
    unsigned Afr[3][2][4][4];
#pragma unroll
    for (int ch = 0; ch < 3; ch++) {
        const float* G = Gtab[ch];
#pragma unroll
        for (int mt = 0; mt < 2; mt++) {
#pragma unroll
            for (int k4 = 0; k4 < 4; k4++) {
                int r0 = w * 32 + mt * 16 + gid;
                int c0 = k4 * 8 + tig;
                Afr[ch][mt][k4][0] = tf32r(G[r0 * 32 + c0]);
                Afr[ch][mt][k4][1] = tf32r(G[(r0 + 8) * 32 + c0]);
                Afr[ch][mt][k4][2] = tf32r(G[r0 * 32 + c0 + 4]);
                Afr[ch][mt][k4][3] = tf32r(G[(r0 + 8) * 32 + c0 + 4]);
            }
        }
    }

    const float4* gs4 = (const float4*)gs;
    const float4* gp4 = (const float4*)gp;
    const float4* gd4 = (const float4*)gd;

    for (int n = blockIdx.x; n < NATOM; n += gridDim.x) {
        int jn[NNJ];
#pragma unroll
        for (int j = 0; j < NNJ; j++) jn[j] = nbr[n * NNJ + j];

#pragma unroll
        for (int r = 0; r < 9; r++) {
            int e = t + r * 128;
            int k = e / 36, pc = e % 36;
            int g = pc >> 2, jj = pc & 3;
            sBu[k * LDB + g * 16 + 12 + jj] = 0u;
        }
        if (t < 96) {
            float4 v = gs4[(size_t)n * 96 + t];
            int j = t >> 3, q = t & 7;
            int base = (q * 4) * LDB + j;
            sBu[base]            = tf32r(v.x);
            sBu[base + LDB]      = tf32r(v.y);
            sBu[base + 2 * LDB]  = tf32r(v.z);
            sBu[base + 3 * LDB]  = tf32r(v.w);
        }
#pragma unroll
        for (int r = 0; r < 3; r++) {
            int e = t + r * 128;
            if (e < 288) {
                float4 v = gp4[(size_t)n * 288 + e];
                float vv[4] = {v.x, v.y, v.z, v.w};
#pragma unroll
                for (int u = 0; u < 4; u++) {
                    int idx = e * 4 + u;
                    int j = idx / 96, rr = idx % 96;
                    int k = rr / 3, a = rr % 3;
                    sBu[k * LDB + 16 + a * 16 + j] = tf32r(vv[u]);
                }
            }
        }
#pragma unroll
        for (int r = 0; r < 4; r++) {
            int e = t + r * 128;
            if (e < 480) {
                float4 v = gd4[(size_t)n * 480 + e];
                float vv[4] = {v.x, v.y, v.z, v.w};
#pragma unroll
                for (int u = 0; u < 4; u++) {
                    int idx = e * 4 + u;
                    int j = idx / 160, rr = idx % 160;
                    int k = rr / 5, a = rr % 5;
                    sBu[k * LDB + 64 + a * 16 + j] = tf32r(vv[u]);
                }
            }
        }
        {
            const float* feaP[3] = {g_sfea, g_pfea, g_dfea};
#pragma unroll
            for (int ch = 0; ch < 3; ch++) {
                float* row = sFea + ch * (128 * FEA_LD) + t * FEA_LD;
#pragma unroll
                for (int j = 0; j < NNJ; j++)
                    row[j] = feaP[ch][(size_t)jn[j] * FD + t];
#pragma unroll
                for (int j = NNJ; j < 16; j++) row[j] = 0.f;
            }
        }

        __syncthreads();

        float P[2][2][9];
#pragma unroll
        for (int mt = 0; mt < 2; mt++)
#pragma unroll
            for (int rr = 0; rr < 2; rr++)
#pragma unroll
                for (int q = 0; q < 9; q++) P[mt][rr][q] = 0.f;

#pragma unroll
        for (int ch = 0; ch < 3; ch++) {
            const int NA = (ch == 0) ? 1 : (ch == 1) ? 3 : 5;
            const int CB = (ch == 0) ? 0 : (ch == 1) ? 16 : 64;
            const int PB = (ch == 0) ? 0 : (ch == 1) ? 1 : 4;
#pragma unroll
            for (int a = 0; a < NA; a++) {
#pragma unroll
                for (int half = 0; half < 2; half++) {
                    int cb = CB + a * 16 + half * 8;
                    unsigned bf[8];
#pragma unroll
                    for (int k4 = 0; k4 < 4; k4++) {
                        bf[2 * k4]     = sBu[(k4 * 8 + tig) * LDB + cb + gid];
                        bf[2 * k4 + 1] = sBu[(k4 * 8 + tig + 4) * LDB + cb + gid];
                    }
                    int j0 = half * 8 + 2 * tig;
#pragma unroll
                    for (int mt = 0; mt < 2; mt++) {
                        float C[4] = {0.f, 0.f, 0.f, 0.f};
#pragma unroll
                        for (int k4 = 0; k4 < 4; k4++)
                            mma_tf32(C, Afr[ch][mt][k4], bf[2 * k4], bf[2 * k4 + 1]);
                        int r = w * 32 + mt * 16 + gid;
                        const float* fr0 = sFea + ch * (128 * FEA_LD) + r * FEA_LD;
                        const float* fr1 = fr0 + 8 * FEA_LD;
                        P[mt][0][PB + a] += C[0] * fr0[j0] + C[1] * fr0[j0 + 1];
                        P[mt][1][PB + a] += C[2] * fr1[j0] + C[3] * fr1[j0 + 1];
                    }
                }
            }
        }

#pragma unroll
        for (int mt = 0; mt < 2; mt++) {
#pragma unroll
            for (int rr = 0; rr < 2; rr++) {
#pragma unroll
                for (int q = 0; q < 9; q++) {
                    float v = P[mt][rr][q];
                    v += __shfl_xor_sync(0xffffffffu, v, 1);
                    v += __shfl_xor_sync(0xffffffffu, v, 2);
                    if (tig == 0) {
                        int r = w * 32 + mt * 16 + rr * 8 + gid;
                        if (q == 0)
                            out[(size_t)n * FD + r] += v;
                        else if (q < 4)
                            g_allp[((size_t)n * 3 + (q - 1)) * FD + r] = v;
                        else
                            g_alld[((size_t)n * 5 + (q - 4)) * FD + r] = v;
                    }
                }
            }
        }

        __syncthreads();
    }
}

// ---------------- K4: rowdot, merged p+d, smem-staged M with reg prefetch ----------------
__global__ __launch_bounds__(256)
void k_quad_mma()
{
    int bid = blockIdx.x;
    int which = (bid >= NP_BLK) ? 1 : 0;
    const float* V = which ? g_alld : g_allp;
    const float* M = which ? g_Md : g_Mp;
    float* rowdot = which ? g_rowd : g_rowp;
    int R = which ? NATOM * 5 : NATOM * 3;
    int row0 = (which ? bid - NP_BLK : bid) * 64;

    __shared__ unsigned smA[64 * LDA];
    __shared__ unsigned smW[16 * 132];
    __shared__ float sPart[2][4][16];

    int t = threadIdx.x;
    int w = t >> 5, lane = t & 31;
    int mt = w & 3, nh = w >> 2;
    int gid = lane >> 2, tig = lane & 3;

#pragma unroll
    for (int r = 0; r < 8; r++) {
        int e = t + r * 256;
        int m = e >> 5, c4 = e & 31;
        int gr = row0 + m;
        float4 v = make_float4(0.f, 0.f, 0.f, 0.f);
        if (gr < R) v = ((const float4*)V)[gr * 32 + c4];
        smA[m * LDA + c4 * 4 + 0] = tf32r(v.x);
        smA[m * LDA + c4 * 4 + 1] = tf32r(v.y);
        smA[m * LDA + c4 * 4 + 2] = tf32r(v.z);
        smA[m * LDA + c4 * 4 + 3] = tf32r(v.w);
    }

    float acc[8][4];
#pragma unroll
    for (int nt = 0; nt < 8; nt++)
#pragma unroll
        for (int c = 0; c < 4; c++) acc[nt][c] = 0.f;

    int kr = t >> 4, c8 = (t & 15) * 8;
    int r0 = mt * 16 + gid;
    const float* mptr = M + kr * FD + c8;

    // preload slice 0
    float4 v0 = *(const float4*)(mptr);
    float4 v1 = *(const float4*)(mptr + 4);

    for (int s = 0; s < 8; s++) {
        int k0 = s * 16;
        __syncthreads();
        smW[kr * 132 + c8 + 0] = tf32r(v0.x);
        smW[kr * 132 + c8 + 1] = tf32r(v0.y);
        smW[kr * 132 + c8 + 2] = tf32r(v0.z);
        smW[kr * 132 + c8 + 3] = tf32r(v0.w);
        smW[kr * 132 + c8 + 4] = tf32r(v1.x);
        smW[kr * 132 + c8 + 5] = tf32r(v1.y);
        smW[kr * 132 + c8 + 6] = tf32r(v1.z);
        smW[kr * 132 + c8 + 7] = tf32r(v1.w);
        if (s < 7) {
            v0 = *(const float4*)(mptr + (s + 1) * 16 * FD);
            v1 = *(const float4*)(mptr + (s + 1) * 16 * FD + 4);
        }
        __syncthreads();

#pragma unroll
        for (int kk = 0; kk < 16; kk += 8) {
            unsigned a[4];
            a[0] = smA[r0 * LDA + k0 + kk + tig];
            a[1] = smA[(r0 + 8) * LDA + k0 + kk + tig];
            a[2] = smA[r0 * LDA + k0 + kk + tig + 4];
            a[3] = smA[(r0 + 8) * LDA + k0 + kk + tig + 4];
#pragma unroll
            for (int nt = 0; nt < 8; nt++) {
                int n0 = nh * 64 + nt * 8;
                unsigned b0 = smW[(kk + tig) * 132 + n0 + gid];
                unsigned b1 = smW[(kk + tig + 4) * 132 + n0 + gid];
                mma_tf32(acc[nt], a, b0, b1);
            }
        }
    }

    // fused row dot vs smem V (tf32-truncated)
    float d0 = 0.f, d1 = 0.f;
    {
        int lr0 = mt * 16 + gid, lr1 = lr0 + 8;
#pragma unroll
        for (int nt = 0; nt < 8; nt++) {
            int c = nh * 64 + nt * 8 + 2 * tig;
            float v00 = __uint_as_float(smA[lr0 * LDA + c]);
            float v01 = __uint_as_float(smA[lr0 * LDA + c + 1]);
            float v10 = __uint_as_float(smA[lr1 * LDA + c]);
            float v11 = __uint_as_float(smA[lr1 * LDA + c + 1]);
            d0 = fmaf(acc[nt][0], v00, fmaf(acc[nt][1], v01, d0));
            d1 = fmaf(acc[nt][2], v10, fmaf(acc[nt][3], v11, d1));
        }
    }
    d0 += __shfl_xor_sync(0xffffffffu, d0, 1);
    d0 += __shfl_xor_sync(0xffffffffu, d0, 2);
    d1 += __shfl_xor_sync(0xffffffffu, d1, 1);
    d1 += __shfl_xor_sync(0xffffffffu, d1, 2);
    if (tig == 0) {
        sPart[nh][mt][gid] = d0;
        sPart[nh][mt][gid + 8] = d1;
    }
    __syncthreads();

    if (t < 64) {
        int mtt = t >> 4, r = t & 15;
        int gr = row0 + mtt * 16 + r;
        if (gr < R) rowdot[gr] = sPart[0][mtt][r] + sPart[1][mtt][r];
    }
}

// ---------------- K5: broadcast scalar add (float4) ----------------
__global__ void k_final(float* __restrict__ out)
{
    int idx4 = blockIdx.x * blockDim.x + threadIdx.x;
    if (idx4 >= NATOM * FD / 4) return;
    int n = idx4 >> 5;
    float s = g_rowp[n * 3 + 0] + g_rowp[n * 3 + 1] + g_rowp[n * 3 + 2]
            + g_rowd[n * 5 + 0] + g_rowd[n * 5 + 1] + g_rowd[n * 5 + 2]
            + g_rowd[n * 5 + 3] + g_rowd[n * 5 + 4];
    float4 o = ((float4*)out)[idx4];
    o.x += s; o.y += s; o.z += s; o.w += s;
    ((float4*)out)[idx4] = o;
}

// ---------------- launch ----------------
extern "C" void kernel_launch(void* const* d_in, const int* in_sizes, int n_in,
                              void* d_out, int out_size)
{
    const float* atom = (const float*)d_in[0];
    const int*   nbr  = (const int*)d_in[1];
    const float* gs   = (const float*)d_in[2];
    const float* gp   = (const float*)d_in[3];
    const float* gd   = (const float*)d_in[4];
    const float* Gs   = (const float*)d_in[5];
    const float* Gp   = (const float*)d_in[6];
    const float* Gd   = (const float*)d_in[7];
    const float* P1   = (const float*)d_in[8];
    const float* P2   = (const float*)d_in[9];
    const float* D1   = (const float*)d_in[10];
    const float* D2   = (const float*)d_in[11];
    float* out = (float*)d_out;

    MlpArgs a;
    for (int ch = 0; ch < 4; ch++) {
        a.wr[ch] = (const float*)d_in[12 + ch * 4 + 0];
        a.br[ch] = (const float*)d_in[12 + ch * 4 + 1];
        a.w1[ch] = (const float*)d_in[12 + ch * 4 + 2];
        a.b1[ch] = (const float*)d_in[12 + ch * 4 + 3];
    }

    k_mmt<<<dim3(16, 2), 128>>>(P1, P2, D1, D2);
    k_resmlp_mma<<<dim3((NATOM + 63) / 64, 4), 256>>>(atom, a, out);
    k_env_mma<<<740, 128>>>(nbr, gs, gp, gd, Gs, Gp, Gd, out);
    k_quad_mma<<<NP_BLK + ND_BLK, 256>>>();
    k_final<<<(NATOM * FD / 4 + 255) / 256, 256>>>(out);
}

// round 15
// speedup vs baseline: 1.1460x; 1.0351x over previous
#include <cuda_runtime.h>

#define NATOM 30000
#define NNJ 12
#define KD 32
#define FD 128
#define LDA 132

// sB layout: [32 k][152 cols]; cols: s [0,16), p a*16+[16,64), d a*16+[64,144), pads zeroed
#define LDB 152
#define SB_FLOATS (32 * LDB)           // 4864
#define FEA_LD 17
#define SFEA_FLOATS (3 * 128 * FEA_LD) // 6528

#define NP_BLK 1407   // ceil(30000*3/64)
#define ND_BLK 2344   // ceil(30000*5/64)

// ---------------- device scratch ----------------
__device__ float g_sfea[NATOM * FD];
__device__ float g_pfea[NATOM * FD];
__device__ float g_dfea[NATOM * FD];
__device__ float g_allp[NATOM * 3 * FD];   // [n][a][f]
__device__ float g_alld[NATOM * 5 * FD];   // [n][a][f]
__device__ float g_Mp[FD * FD];            // P1 @ P2^T
__device__ float g_Md[FD * FD];            // D1 @ D2^T
__device__ float g_rowp[NATOM * 3];
__device__ float g_rowd[NATOM * 5];

__device__ __forceinline__ float siluf(float x) {
    return x / (1.0f + __expf(-x));
}

__device__ __forceinline__ unsigned tf32r(float x) {
    unsigned u;
    asm("cvt.rna.tf32.f32 %0, %1;" : "=r"(u) : "f"(x));
    return u;
}

__device__ __forceinline__ void mma_tf32(float c[4], const unsigned a[4],
                                         unsigned b0, unsigned b1) {
    asm volatile(
        "mma.sync.aligned.m16n8k8.row.col.f32.tf32.tf32.f32 "
        "{%0,%1,%2,%3},{%4,%5,%6,%7},{%8,%9},{%0,%1,%2,%3};"
        : "+f"(c[0]), "+f"(c[1]), "+f"(c[2]), "+f"(c[3])
        : "r"(a[0]), "r"(a[1]), "r"(a[2]), "r"(a[3]), "r"(b0), "r"(b1));
}

// ---------------- K1: Mp = P1 @ P2^T, Md = D1 @ D2^T ----------------
__global__ __launch_bounds__(128)
void k_mmt(const float* __restrict__ P1, const float* __restrict__ P2,
           const float* __restrict__ D1, const float* __restrict__ D2)
{
    const float* A = blockIdx.y ? D1 : P1;
    const float* B = blockIdx.y ? D2 : P2;
    float* M = blockIdx.y ? g_Md : g_Mp;

    __shared__ float smA[8 * FD];
    __shared__ float smB[16 * LDA];
    int t = threadIdx.x;
    int i0 = blockIdx.x * 8;

#pragma unroll
    for (int r = 0; r < 2; r++) {
        int e = t + r * 128;
        ((float4*)smA)[e] = ((const float4*)A)[i0 * 32 + e];
    }

    float acc[8];
#pragma unroll
    for (int i = 0; i < 8; i++) acc[i] = 0.f;

    for (int g0 = 0; g0 < FD; g0 += 16) {
        __syncthreads();
#pragma unroll
        for (int r = 0; r < 4; r++) {
            int e = t + r * 128;
            int j = e >> 2, q = e & 3;
            float4 v = ((const float4*)B)[j * 32 + (g0 >> 2) + q];
            smB[(q * 4 + 0) * LDA + j] = v.x;
            smB[(q * 4 + 1) * LDA + j] = v.y;
            smB[(q * 4 + 2) * LDA + j] = v.z;
            smB[(q * 4 + 3) * LDA + j] = v.w;
        }
        __syncthreads();
#pragma unroll
        for (int gl = 0; gl < 16; gl++) {
            float b = smB[gl * LDA + t];
#pragma unroll
            for (int i = 0; i < 8; i++)
                acc[i] = fmaf(smA[i * FD + g0 + gl], b, acc[i]);
        }
    }
#pragma unroll
    for (int i = 0; i < 8; i++) M[(i0 + i) * FD + t] = acc[i];
}

// ---------------- K2: fused ResMLP via tf32 mma, reg-prefetched W staging ----------------
struct MlpArgs {
    const float* wr[4]; const float* br[4];
    const float* w1[4]; const float* b1[4];
};

__device__ __forceinline__ void mma_gemm_pass(const float* __restrict__ W,
                                              float acc[8][4],
                                              const unsigned* smA, unsigned* smW,
                                              int t, int mt, int nh, int gid, int tig)
{
#pragma unroll
    for (int nt = 0; nt < 8; nt++)
#pragma unroll
        for (int c = 0; c < 4; c++) acc[nt][c] = 0.f;

    int wrow = t >> 1, wq = (t & 1) * 8;
    int r0 = mt * 16 + gid;
    const float* wptr = W + wrow * FD + wq;

    float4 va = *(const float4*)(wptr);
    float4 vb = *(const float4*)(wptr + 4);

    for (int s = 0; s < 8; s++) {
        int k0 = s * 16;
        __syncthreads();
        smW[(wq + 0) * 132 + wrow] = tf32r(va.x);
        smW[(wq + 1) * 132 + wrow] = tf32r(va.y);
        smW[(wq + 2) * 132 + wrow] = tf32r(va.z);
        smW[(wq + 3) * 132 + wrow] = tf32r(va.w);
        smW[(wq + 4) * 132 + wrow] = tf32r(vb.x);
        smW[(wq + 5) * 132 + wrow] = tf32r(vb.y);
        smW[(wq + 6) * 132 + wrow] = tf32r(vb.z);
        smW[(wq + 7) * 132 + wrow] = tf32r(vb.w);
        if (s < 7) {
            va = *(const float4*)(wptr + (s + 1) * 16);
            vb = *(const float4*)(wptr + (s + 1) * 16 + 4);
        }
        __syncthreads();

#pragma unroll
        for (int kk = 0; kk < 16; kk += 8) {
            unsigned a[4];
            a[0] = smA[r0 * LDA + k0 + kk + tig];
            a[1] = smA[(r0 + 8) * LDA + k0 + kk + tig];
            a[2] = smA[r0 * LDA + k0 + kk + tig + 4];
            a[3] = smA[(r0 + 8) * LDA + k0 + kk + tig + 4];
#pragma unroll
            for (int nt = 0; nt < 8; nt++) {
                int n0 = nh * 64 + nt * 8;
                unsigned b0 = smW[(kk + tig) * 132 + n0 + gid];
                unsigned b1 = smW[(kk + tig + 4) * 132 + n0 + gid];
                mma_tf32(acc[nt], a, b0, b1);
            }
        }
    }
    __syncthreads();
}

__global__ __launch_bounds__(256)
void k_resmlp_mma(const float* __restrict__ x, MlpArgs args, float* __restrict__ out)
{
    __shared__ unsigned smA[64 * LDA];
    __shared__ unsigned smW[16 * 132];

    int ch = blockIdx.y;
    const float* wr = args.wr[ch];
    const float* brp = args.br[ch];
    const float* w1 = args.w1[ch];
    const float* b1p = args.b1[ch];
    float* dst = (ch == 0) ? out : (ch == 1) ? g_sfea : (ch == 2) ? g_pfea : g_dfea;

    int row0 = blockIdx.x * 64;
    int t = threadIdx.x;
    int w = t >> 5, lane = t & 31;
    int mt = w & 3, nh = w >> 2;
    int gid = lane >> 2, tig = lane & 3;

#pragma unroll
    for (int r = 0; r < 8; r++) {
        int e = t + r * 256;
        int m = e >> 5, c4 = e & 31;
        int gr = row0 + m;
        float4 v = make_float4(0.f, 0.f, 0.f, 0.f);
        if (gr < NATOM) v = ((const float4*)x)[gr * 32 + c4];
        smA[m * LDA + c4 * 4 + 0] = tf32r(siluf(v.x));
        smA[m * LDA + c4 * 4 + 1] = tf32r(siluf(v.y));
        smA[m * LDA + c4 * 4 + 2] = tf32r(siluf(v.z));
        smA[m * LDA + c4 * 4 + 3] = tf32r(siluf(v.w));
    }

    float acc[8][4];
    mma_gemm_pass(wr, acc, smA, smW, t, mt, nh, gid, tig);

    {
        int r0 = row0 + mt * 16 + gid;
        int r1 = r0 + 8;
#pragma unroll
        for (int nt = 0; nt < 8; nt++) {
            int c = nh * 64 + nt * 8 + 2 * tig;
            float2 br2 = *(const float2*)&brp[c];
            float2 x0 = make_float2(0.f, 0.f), x1 = x0;
            if (r0 < NATOM) x0 = *(const float2*)&x[r0 * FD + c];
            if (r1 < NATOM) x1 = *(const float2*)&x[r1 * FD + c];
            int lr0 = mt * 16 + gid, lr1 = lr0 + 8;
            smA[lr0 * LDA + c]     = tf32r(siluf(acc[nt][0] + x0.x + br2.x));
            smA[lr0 * LDA + c + 1] = tf32r(siluf(acc[nt][1] + x0.y + br2.y));
            smA[lr1 * LDA + c]     = tf32r(siluf(acc[nt][2] + x1.x + br2.x));
            smA[lr1 * LDA + c + 1] = tf32r(siluf(acc[nt][3] + x1.y + br2.y));
        }
    }

    mma_gemm_pass(w1, acc, smA, smW, t, mt, nh, gid, tig);

    {
        int r0 = row0 + mt * 16 + gid;
        int r1 = r0 + 8;
#pragma unroll
        for (int nt = 0; nt < 8; nt++) {
            int c = nh * 64 + nt * 8 + 2 * tig;
            float2 b2 = *(const float2*)&b1p[c];
            if (r0 < NATOM)
                *(float2*)&dst[r0 * FD + c] =
                    make_float2(acc[nt][0] + b2.x, acc[nt][1] + b2.y);
            if (r1 < NATOM)
                *(float2*)&dst[r1 * FD + c] =
                    make_float2(acc[nt][2] + b2.x, acc[nt][3] + b2.y);
        }
    }
}

// ---------------- K3: env via tf32 mma — 256 threads, 8 warps (mt=1), reg prefetch ----------------
__global__ __launch_bounds__(256)
void k_env_mma(const int* __restrict__ nbr,
               const float* __restrict__ gs, const float* __restrict__ gp,
               const float* __restrict__ gd,
               const float* __restrict__ Gs, const float* __restrict__ Gp,
               const float* __restrict__ Gd,
               float* __restrict__ out)
{
    __shared__ unsigned sBu[SB_FLOATS];   // 19456 B
    __shared__ float sFea[SFEA_FLOATS];   // 26112 B  [3][128][FEA_LD]

    int t = threadIdx.x;
    int w = t >> 5;                 // warp 0..7: covers f-rows [w*16, w*16+16)
    int lane = t & 31;
    int gid = lane >> 2;
    int tig = lane & 3;

    // zero once: pads never overwritten afterwards
    for (int e = t; e < SB_FLOATS; e += 256) sBu[e] = 0u;
    for (int e = t; e < SFEA_FLOATS; e += 256) sFea[e] = 0.f;

    // A fragments: 48 regs (halved vs 4-warp layout)
    const float* Gtab[3] = {Gs, Gp, Gd};
    unsigned Afr[3][4][4];
#pragma unroll
    for (int ch = 0; ch < 3; ch++) {
        const float* G = Gtab[ch];
        int r0 = w * 16 + gid;
#pragma unroll
        for (int k4 = 0; k4 < 4; k4++) {
            int c0 = k4 * 8 + tig;
            Afr[ch][k4][0] = tf32r(G[r0 * 32 + c0]);
            Afr[ch][k4][1] = tf32r(G[(r0 + 8) * 32 + c0]);
            Afr[ch][k4][2] = tf32r(G[r0 * 32 + c0 + 4]);
            Afr[ch][k4][3] = tf32r(G[(r0 + 8) * 32 + c0 + 4]);
        }
    }

    const float4* gs4 = (const float4*)gs;
    const float4* gp4 = (const float4*)gp;
    const float4* gd4 = (const float4*)gd;

    // ---- prologue prefetch (registers) ----
    int n = blockIdx.x;
    int4 jA, jB, jC;
    float4 pgs, pgp[2], pgd[2];
    {
        const int4* nb4 = (const int4*)(nbr + n * NNJ);
        jA = nb4[0]; jB = nb4[1]; jC = nb4[2];
        if (t < 96) pgs = gs4[(size_t)n * 96 + t];
        pgp[0] = gp4[(size_t)n * 288 + t];
        if (t < 32) pgp[1] = gp4[(size_t)n * 288 + t + 256];
        pgd[0] = gd4[(size_t)n * 480 + t];
        if (t < 224) pgd[1] = gd4[(size_t)n * 480 + t + 256];
    }

    for (; n < NATOM; n += gridDim.x) {
        int jn[NNJ] = {jA.x, jA.y, jA.z, jA.w, jB.x, jB.y, jB.z, jB.w,
                       jC.x, jC.y, jC.z, jC.w};

        // fea gather: thread (jh = t>>7, f = t&127) loads j = jh*6 .. jh*6+5
        {
            int f = t & 127;
            int jh = (t >> 7) * 6;
            const float* feaP[3] = {g_sfea, g_pfea, g_dfea};
#pragma unroll
            for (int ch = 0; ch < 3; ch++) {
                float* row = sFea + ch * (128 * FEA_LD) + f * FEA_LD + jh;
#pragma unroll
                for (int jj = 0; jj < 6; jj++)
                    row[jj] = feaP[ch][(size_t)jn[jh + jj] * FD + f];
            }
        }
        // gs from regs -> cols [0,12)
        if (t < 96) {
            int j = t >> 3, q = t & 7;
            int base = (q * 4) * LDB + j;
            sBu[base]           = tf32r(pgs.x);
            sBu[base + LDB]     = tf32r(pgs.y);
            sBu[base + 2 * LDB] = tf32r(pgs.z);
            sBu[base + 3 * LDB] = tf32r(pgs.w);
        }
        // gp from regs -> cols 16 + a*16 + j
#pragma unroll
        for (int r = 0; r < 2; r++) {
            int e = t + r * 256;
            if (e < 288) {
                float vv[4] = {pgp[r].x, pgp[r].y, pgp[r].z, pgp[r].w};
#pragma unroll
                for (int u = 0; u < 4; u++) {
                    int idx = e * 4 + u;
                    int j = idx / 96, rr = idx % 96;
                    int k = rr / 3, a = rr % 3;
                    sBu[k * LDB + 16 + a * 16 + j] = tf32r(vv[u]);
                }
            }
        }
        // gd from regs -> cols 64 + a*16 + j
#pragma unroll
        for (int r = 0; r < 2; r++) {
            int e = t + r * 256;
            if (e < 480) {
                float vv[4] = {pgd[r].x, pgd[r].y, pgd[r].z, pgd[r].w};
#pragma unroll
                for (int u = 0; u < 4; u++) {
                    int idx = e * 4 + u;
                    int j = idx / 160, rr = idx % 160;
                    int k = rr / 5, a = rr % 5;
                    sBu[k * LDB + 64 + a * 16 + j] = tf32r(vv[u]);
                }
            }
        }
        __syncthreads();

        // ---- prefetch next atom during compute ----
        int nn = n + gridDim.x;
        if (nn < NATOM) {
            const int4* nb4 = (const int4*)(nbr + nn * NNJ);
            jA = nb4[0]; jB = nb4[1]; jC = nb4[2];
            if (t < 96) pgs = gs4[(size_t)nn * 96 + t];
            pgp[0] = gp4[(size_t)nn * 288 + t];
            if (t < 32) pgp[1] = gp4[(size_t)nn * 288 + t + 256];
            pgd[0] = gd4[(size_t)nn * 480 + t];
            if (t < 224) pgd[1] = gd4[(size_t)nn * 480 + t + 256];
        }

        // ---- compute: warp w handles f-rows [w*16, w*16+16), all 9 a-slices ----
#pragma unroll
        for (int ch = 0; ch < 3; ch++) {
            const int NA = (ch == 0) ? 1 : (ch == 1) ? 3 : 5;
            const int CB = (ch == 0) ? 0 : (ch == 1) ? 16 : 64;
            const float* fbase = sFea + ch * (128 * FEA_LD);
#pragma unroll
            for (int a = 0; a < NA; a++) {
                float Pl[2] = {0.f, 0.f};
#pragma unroll
                for (int half = 0; half < 2; half++) {
                    int cb = CB + a * 16 + half * 8;
                    unsigned bf[8];
#pragma unroll
                    for (int k4 = 0; k4 < 4; k4++) {
                        bf[2 * k4]     = sBu[(k4 * 8 + tig) * LDB + cb + gid];
                        bf[2 * k4 + 1] = sBu[(k4 * 8 + tig + 4) * LDB + cb + gid];
                    }
                    int j0 = half * 8 + 2 * tig;
                    float C[4] = {0.f, 0.f, 0.f, 0.f};
#pragma unroll
                    for (int k4 = 0; k4 < 4; k4++)
                        mma_tf32(C, Afr[ch][k4], bf[2 * k4], bf[2 * k4 + 1]);
                    int r = w * 16 + gid;
                    const float* fr0 = fbase + r * FEA_LD;
                    const float* fr1 = fr0 + 8 * FEA_LD;
                    Pl[0] += C[0] * fr0[j0] + C[1] * fr0[j0 + 1];
                    Pl[1] += C[2] * fr1[j0] + C[3] * fr1[j0 + 1];
                }
                // reduce over quad + store this (ch, a)
#pragma unroll
                for (int rr = 0; rr < 2; rr++) {
                    float v = Pl[rr];
                    v += __shfl_xor_sync(0xffffffffu, v, 1);
                    v += __shfl_xor_sync(0xffffffffu, v, 2);
                    if (tig == 0) {
                        int r = w * 16 + rr * 8 + gid;
                        if (ch == 0)
                            out[(size_t)n * FD + r] += v;
                        else if (ch == 1)
                            g_allp[((size_t)n * 3 + a) * FD + r] = v;
                        else
                            g_alld[((size_t)n * 5 + a) * FD + r] = v;
                    }
                }
            }
        }

        __syncthreads();
    }
}

// ---------------- K4: rowdot, merged p+d, smem-staged M with reg prefetch ----------------
__global__ __launch_bounds__(256)
void k_quad_mma()
{
    int bid = blockIdx.x;
    int which = (bid >= NP_BLK) ? 1 : 0;
    const float* V = which ? g_alld : g_allp;
    const float* M = which ? g_Md : g_Mp;
    float* rowdot = which ? g_rowd : g_rowp;
    int R = which ? NATOM * 5 : NATOM * 3;
    int row0 = (which ? bid - NP_BLK : bid) * 64;

    __shared__ unsigned smA[64 * LDA];
    __shared__ unsigned smW[16 * 132];
    __shared__ float sPart[2][4][16];

    int t = threadIdx.x;
    int w = t >> 5, lane = t & 31;
    int mt = w & 3, nh = w >> 2;
    int gid = lane >> 2, tig = lane & 3;

#pragma unroll
    for (int r = 0; r < 8; r++) {
        int e = t + r * 256;
        int m = e >> 5, c4 = e & 31;
        int gr = row0 + m;
        float4 v = make_float4(0.f, 0.f, 0.f, 0.f);
        if (gr < R) v = ((const float4*)V)[gr * 32 + c4];
        smA[m * LDA + c4 * 4 + 0] = tf32r(v.x);
        smA[m * LDA + c4 * 4 + 1] = tf32r(v.y);
        smA[m * LDA + c4 * 4 + 2] = tf32r(v.z);
        smA[m * LDA + c4 * 4 + 3] = tf32r(v.w);
    }

    float acc[8][4];
#pragma unroll
    for (int nt = 0; nt < 8; nt++)
#pragma unroll
        for (int c = 0; c < 4; c++) acc[nt][c] = 0.f;

    int kr = t >> 4, c8 = (t & 15) * 8;
    int r0 = mt * 16 + gid;
    const float* mptr = M + kr * FD + c8;

    float4 v0 = *(const float4*)(mptr);
    float4 v1 = *(const float4*)(mptr + 4);

    for (int s = 0; s < 8; s++) {
        int k0 = s * 16;
        __syncthreads();
        smW[kr * 132 + c8 + 0] = tf32r(v0.x);
        smW[kr * 132 + c8 + 1] = tf32r(v0.y);
        smW[kr * 132 + c8 + 2] = tf32r(v0.z);
        smW[kr * 132 + c8 + 3] = tf32r(v0.w);
        smW[kr * 132 + c8 + 4] = tf32r(v1.x);
        smW[kr * 132 + c8 + 5] = tf32r(v1.y);
        smW[kr * 132 + c8 + 6] = tf32r(v1.z);
        smW[kr * 132 + c8 + 7] = tf32r(v1.w);
        if (s < 7) {
            v0 = *(const float4*)(mptr + (s + 1) * 16 * FD);
            v1 = *(const float4*)(mptr + (s + 1) * 16 * FD + 4);
        }
        __syncthreads();

#pragma unroll
        for (int kk = 0; kk < 16; kk += 8) {
            unsigned a[4];
            a[0] = smA[r0 * LDA + k0 + kk + tig];
            a[1] = smA[(r0 + 8) * LDA + k0 + kk + tig];
            a[2] = smA[r0 * LDA + k0 + kk + tig + 4];
            a[3] = smA[(r0 + 8) * LDA + k0 + kk + tig + 4];
#pragma unroll
            for (int nt = 0; nt < 8; nt++) {
                int n0 = nh * 64 + nt * 8;
                unsigned b0 = smW[(kk + tig) * 132 + n0 + gid];
                unsigned b1 = smW[(kk + tig + 4) * 132 + n0 + gid];
                mma_tf32(acc[nt], a, b0, b1);
            }
        }
    }

    float d0 = 0.f, d1 = 0.f;
    {
        int lr0 = mt * 16 + gid, lr1 = lr0 + 8;
#pragma unroll
        for (int nt = 0; nt < 8; nt++) {
            int c = nh * 64 + nt * 8 + 2 * tig;
            float v00 = __uint_as_float(smA[lr0 * LDA + c]);
            float v01 = __uint_as_float(smA[lr0 * LDA + c + 1]);
            float v10 = __uint_as_float(smA[lr1 * LDA + c]);
            float v11 = __uint_as_float(smA[lr1 * LDA + c + 1]);
            d0 = fmaf(acc[nt][0], v00, fmaf(acc[nt][1], v01, d0));
            d1 = fmaf(acc[nt][2], v10, fmaf(acc[nt][3], v11, d1));
        }
    }
    d0 += __shfl_xor_sync(0xffffffffu, d0, 1);
    d0 += __shfl_xor_sync(0xffffffffu, d0, 2);
    d1 += __shfl_xor_sync(0xffffffffu, d1, 1);
    d1 += __shfl_xor_sync(0xffffffffu, d1, 2);
    if (tig == 0) {
        sPart[nh][mt][gid] = d0;
        sPart[nh][mt][gid + 8] = d1;
    }
    __syncthreads();

    if (t < 64) {
        int mtt = t >> 4, r = t & 15;
        int gr = row0 + mtt * 16 + r;
        if (gr < R) rowdot[gr] = sPart[0][mtt][r] + sPart[1][mtt][r];
    }
}

// ---------------- K5: broadcast scalar add (float4) ----------------
__global__ void k_final(float* __restrict__ out)
{
    int idx4 = blockIdx.x * blockDim.x + threadIdx.x;
    if (idx4 >= NATOM * FD / 4) return;
    int n = idx4 >> 5;
    float s = g_rowp[n * 3 + 0] + g_rowp[n * 3 + 1] + g_rowp[n * 3 + 2]
            + g_rowd[n * 5 + 0] + g_rowd[n * 5 + 1] + g_rowd[n * 5 + 2]
            + g_rowd[n * 5 + 3] + g_rowd[n * 5 + 4];
    float4 o = ((float4*)out)[idx4];
    o.x += s; o.y += s; o.z += s; o.w += s;
    ((float4*)out)[idx4] = o;
}

// ---------------- launch ----------------
extern "C" void kernel_launch(void* const* d_in, const int* in_sizes, int n_in,
                              void* d_out, int out_size)
{
    const float* atom = (const float*)d_in[0];
    const int*   nbr  = (const int*)d_in[1];
    const float* gs   = (const float*)d_in[2];
    const float* gp   = (const float*)d_in[3];
    const float* gd   = (const float*)d_in[4];
    const float* Gs   = (const float*)d_in[5];
    const float* Gp   = (const float*)d_in[6];
    const float* Gd   = (const float*)d_in[7];
    const float* P1   = (const float*)d_in[8];
    const float* P2   = (const float*)d_in[9];
    const float* D1   = (const float*)d_in[10];
    const float* D2   = (const float*)d_in[11];
    float* out = (float*)d_out;

    MlpArgs a;
    for (int ch = 0; ch < 4; ch++) {
        a.wr[ch] = (const float*)d_in[12 + ch * 4 + 0];
        a.br[ch] = (const float*)d_in[12 + ch * 4 + 1];
        a.w1[ch] = (const float*)d_in[12 + ch * 4 + 2];
        a.b1[ch] = (const float*)d_in[12 + ch * 4 + 3];
    }

    k_mmt<<<dim3(16, 2), 128>>>(P1, P2, D1, D2);
    k_resmlp_mma<<<dim3((NATOM + 63) / 64, 4), 256>>>(atom, a, out);
    k_env_mma<<<296, 256>>>(nbr, gs, gp, gd, Gs, Gp, Gd, out);
    k_quad_mma<<<NP_BLK + ND_BLK, 256>>>();
    k_final<<<(NATOM * FD / 4 + 255) / 256, 256>>>(out);
}